// round 2
// baseline (speedup 1.0000x reference)
#include <cuda_runtime.h>
#include <cuda_bf16.h>

// ---------------------------------------------------------------------------
// LSTMActorCritic: NSEQ=256, T=1024, OBS=128, ACT=16, H=64, N=262144
//
// Plan:
//  K1 mlp_gx_kernel : per-row MLP (128->64->64, tanh) fused with the input-side
//                     LSTM gate GEMM gx = feat @ Wih.T + bih + bhh  (both
//                     branches via blockIdx.y). fp32 with packed fma.rn.f32x2.
//  K2 lstm_kernel   : 256 blocks, each owns 2 sequences of ONE lstm for all
//                     1024 steps. Recurrent h@Whh.T with weights packed in
//                     registers (f32x2 over K), h broadcast from smem.
//                     Episode-reset masking folded into h/c writeback.
//  K3 heads_kernel  : logits/log_softmax/logprob/entropy + value.
// ---------------------------------------------------------------------------

typedef unsigned long long ull;

#define NSEQ   256
#define TLEN   1024
#define NROWS  262144      // NSEQ*TLEN
#define OBSD   128
#define HID    64
#define GATES  256         // 4*HID
#define ACT    16

// Scratch (no cudaMalloc allowed): gate pre-activations and LSTM outputs.
__device__ float d_gx [2ull * NROWS * GATES];   // 536 MB
__device__ float d_lat[2ull * NROWS * HID];     // 134 MB

// ---------------- packed fp32x2 helpers ----------------
__device__ __forceinline__ ull pk2(float lo, float hi) {
    ull r; asm("mov.b64 %0,{%1,%2};" : "=l"(r) : "f"(lo), "f"(hi)); return r;
}
__device__ __forceinline__ float hsum2(ull v) {
    float a, b; asm("mov.b64 {%0,%1}, %2;" : "=f"(a), "=f"(b) : "l"(v)); return a + b;
}
__device__ __forceinline__ void fma2(ull &acc, ull a, ull b) {
    asm("fma.rn.f32x2 %0,%1,%2,%0;" : "+l"(acc) : "l"(a), "l"(b));
}

__device__ __forceinline__ float sigmoidf_(float x) {
    return __fdividef(1.f, 1.f + __expf(-x));
}
__device__ __forceinline__ float tanhf_(float x) {
    float e = __expf(-2.f * fabsf(x));
    float t = __fdividef(1.f - e, 1.f + e);
    return copysignf(t, x);
}

// ---------------------------------------------------------------------------
// K1: MLP + input-gate precompute. grid (2048, 2), block 128. One row/thread.
// smem: W1 (8192 f) + W2 (4096 f) + Wih (16384 f) = 114688 B (dynamic).
// ---------------------------------------------------------------------------
extern "C" __global__ void __launch_bounds__(128)
mlp_gx_kernel(const float* __restrict__ obs,
              const float* __restrict__ Wp1, const float* __restrict__ bp1,
              const float* __restrict__ Wp2, const float* __restrict__ bp2,
              const float* __restrict__ Wv1, const float* __restrict__ bv1,
              const float* __restrict__ Wv2, const float* __restrict__ bv2,
              const float* __restrict__ Wih_pi, const float* __restrict__ bih_pi,
              const float* __restrict__ bhh_pi,
              const float* __restrict__ Wih_vf, const float* __restrict__ bih_vf,
              const float* __restrict__ bhh_vf)
{
    extern __shared__ float smem[];
    float* w1s  = smem;            // 8192
    float* w2s  = w1s + 8192;      // 4096
    float* wihs = w2s + 4096;      // 16384

    const int tid    = threadIdx.x;
    const int branch = blockIdx.y;

    const float* W1  = branch ? Wv1 : Wp1;
    const float* b1  = branch ? bv1 : bp1;
    const float* W2  = branch ? Wv2 : Wp2;
    const float* b2  = branch ? bv2 : bp2;
    const float* Wih = branch ? Wih_vf : Wih_pi;
    const float* bih = branch ? bih_vf : bih_pi;
    const float* bhh = branch ? bhh_vf : bhh_pi;
    float* gx = d_gx + (size_t)branch * NROWS * GATES;

    for (int i = tid; i < 8192;  i += 128) w1s[i]  = W1[i];
    for (int i = tid; i < 4096;  i += 128) w2s[i]  = W2[i];
    for (int i = tid; i < 16384; i += 128) wihs[i] = Wih[i];
    __syncthreads();

    const int row = blockIdx.x * 128 + tid;

    // obs row -> 64 packed pairs in registers
    ull x2[64];
    {
        const float4* op = (const float4*)(obs + (size_t)row * OBSD);
        #pragma unroll
        for (int i = 0; i < 32; i++) {
            float4 v = op[i];
            x2[2*i]   = pk2(v.x, v.y);
            x2[2*i+1] = pk2(v.z, v.w);
        }
    }

    // Layer 1: 64 outputs, K=128
    ull t1p[32];
    #pragma unroll 1
    for (int j = 0; j < 64; j += 2) {
        const ulonglong2* wr0 = (const ulonglong2*)(w1s + j * 128);
        const ulonglong2* wr1 = (const ulonglong2*)(w1s + (j + 1) * 128);
        ull a0 = 0, a1 = 0, b0 = 0, b1_ = 0;
        #pragma unroll
        for (int kk = 0; kk < 32; kk++) {
            ulonglong2 wA = wr0[kk]; ulonglong2 wB = wr1[kk];
            fma2(a0,  wA.x, x2[2*kk]);   fma2(a1,  wA.y, x2[2*kk+1]);
            fma2(b0,  wB.x, x2[2*kk]);   fma2(b1_, wB.y, x2[2*kk+1]);
        }
        float s0 = hsum2(a0) + hsum2(a1) + __ldg(&b1[j]);
        float s1 = hsum2(b0) + hsum2(b1_) + __ldg(&b1[j + 1]);
        t1p[j >> 1] = pk2(tanhf_(s0), tanhf_(s1));
    }

    // Layer 2: 64 outputs, K=64
    ull fp[32];
    #pragma unroll 1
    for (int j = 0; j < 64; j += 2) {
        const ulonglong2* wr0 = (const ulonglong2*)(w2s + j * 64);
        const ulonglong2* wr1 = (const ulonglong2*)(w2s + (j + 1) * 64);
        ull a0 = 0, a1 = 0, b0 = 0, b1_ = 0;
        #pragma unroll
        for (int kk = 0; kk < 16; kk++) {
            ulonglong2 wA = wr0[kk]; ulonglong2 wB = wr1[kk];
            fma2(a0,  wA.x, t1p[2*kk]);   fma2(a1,  wA.y, t1p[2*kk+1]);
            fma2(b0,  wB.x, t1p[2*kk]);   fma2(b1_, wB.y, t1p[2*kk+1]);
        }
        float s0 = hsum2(a0) + hsum2(a1) + __ldg(&b2[j]);
        float s1 = hsum2(b0) + hsum2(b1_) + __ldg(&b2[j + 1]);
        fp[j >> 1] = pk2(tanhf_(s0), tanhf_(s1));
    }

    // Gate GEMM: 256 outputs, K=64, biases folded in
    float2* gxo = (float2*)(gx + (size_t)row * GATES);
    #pragma unroll 1
    for (int j = 0; j < 256; j += 2) {
        const ulonglong2* wr0 = (const ulonglong2*)(wihs + j * 64);
        const ulonglong2* wr1 = (const ulonglong2*)(wihs + (j + 1) * 64);
        ull a0 = 0, a1 = 0, b0 = 0, b1_ = 0;
        #pragma unroll
        for (int kk = 0; kk < 16; kk++) {
            ulonglong2 wA = wr0[kk]; ulonglong2 wB = wr1[kk];
            fma2(a0,  wA.x, fp[2*kk]);   fma2(a1,  wA.y, fp[2*kk+1]);
            fma2(b0,  wB.x, fp[2*kk]);   fma2(b1_, wB.y, fp[2*kk+1]);
        }
        float g0 = hsum2(a0) + hsum2(a1) + __ldg(&bih[j])     + __ldg(&bhh[j]);
        float g1 = hsum2(b0) + hsum2(b1_) + __ldg(&bih[j + 1]) + __ldg(&bhh[j + 1]);
        gxo[j >> 1] = make_float2(g0, g1);
    }
}

// ---------------------------------------------------------------------------
// K2: recurrent loop. grid 256 blocks (bit7 = lstm, low bits = seq pair),
// 256 threads: thread j computes gate j for both of its 2 sequences (shared
// weight row in registers). Threads 0..127 apply the elementwise update.
// ---------------------------------------------------------------------------
extern "C" __global__ void __launch_bounds__(256, 2)
lstm_kernel(const float* __restrict__ Whh_pi, const float* __restrict__ Whh_vf,
            const float* __restrict__ eps,
            const float* __restrict__ h0_pi, const float* __restrict__ c0_pi,
            const float* __restrict__ h0_vf, const float* __restrict__ c0_vf)
{
    const int tid  = threadIdx.x;
    const int lstm = blockIdx.x >> 7;
    const int sp   = blockIdx.x & 127;
    const int seqA = sp * 2, seqB = sp * 2 + 1;

    const float* Whh = lstm ? Whh_vf : Whh_pi;
    const float* h0  = lstm ? h0_vf  : h0_pi;
    const float* c0  = lstm ? c0_vf  : c0_pi;
    const float* gx  = d_gx  + (size_t)lstm * NROWS * GATES;
    float*       lat = d_lat + (size_t)lstm * NROWS * HID;

    __shared__ __align__(16) float hs[2][HID];
    __shared__ float gs[2][GATES];

    // Whh row tid -> 32 packed pairs in registers
    ull wv[32];
    {
        const float4* wp = (const float4*)(Whh + tid * HID);
        #pragma unroll
        for (int i = 0; i < 16; i++) {
            float4 v = wp[i];
            wv[2*i]   = pk2(v.x, v.y);
            wv[2*i+1] = pk2(v.z, v.w);
        }
    }

    const int s = tid >> 6, j = tid & 63;      // valid for tid < 128
    const int myseq = seqA + s;
    float c = 0.f, enext = 0.f;
    if (tid < 128) {
        float m = 1.f - eps[(size_t)myseq * TLEN];
        hs[s][j] = h0[myseq * HID + j] * m;
        c        = c0[myseq * HID + j] * m;
        enext    = eps[(size_t)myseq * TLEN + 1];
    }
    __syncthreads();

    float gA = gx[((size_t)seqA * TLEN) * GATES + tid];
    float gB = gx[((size_t)seqB * TLEN) * GATES + tid];

    const ulonglong2* hA2 = (const ulonglong2*)hs[0];
    const ulonglong2* hB2 = (const ulonglong2*)hs[1];

    for (int t = 0; t < TLEN; t++) {
        ull a0 = 0, a1 = 0, b0 = 0, b1_ = 0;
        #pragma unroll
        for (int kk = 0; kk < 16; kk++) {
            ulonglong2 ha = hA2[kk]; ulonglong2 hb = hB2[kk];
            fma2(a0,  wv[2*kk],   ha.x);  fma2(a1,  wv[2*kk+1], ha.y);
            fma2(b0,  wv[2*kk],   hb.x);  fma2(b1_, wv[2*kk+1], hb.y);
        }
        float gateA = gA + hsum2(a0) + hsum2(a1);
        float gateB = gB + hsum2(b0) + hsum2(b1_);

        // software-pipelined prefetch for step t+1 / mask for t+2
        if (t < TLEN - 1) {
            gA = gx[((size_t)seqA * TLEN + t + 1) * GATES + tid];
            gB = gx[((size_t)seqB * TLEN + t + 1) * GATES + tid];
        }
        float e2 = 0.f;
        if (tid < 128 && t < TLEN - 2) e2 = eps[(size_t)myseq * TLEN + t + 2];

        gs[0][tid] = gateA;
        gs[1][tid] = gateB;
        __syncthreads();

        if (tid < 128) {
            float gi = gs[s][j],       gf = gs[s][64 + j];
            float gg = gs[s][128 + j], go = gs[s][192 + j];
            c = sigmoidf_(gf) * c + sigmoidf_(gi) * tanhf_(gg);
            float h = sigmoidf_(go) * tanhf_(c);
            lat[((size_t)myseq * TLEN + t) * HID + j] = h;
            float m = 1.f - enext;    // mask for step t+1 (unused garbage at t=1023 is never read)
            c *= m;
            hs[s][j] = h * m;
            enext = e2;
        }
        __syncthreads();
    }
}

// ---------------------------------------------------------------------------
// K3: heads. grid 2048 blocks, 128 threads, block handles 128 rows.
// ---------------------------------------------------------------------------
extern "C" __global__ void __launch_bounds__(128)
heads_kernel(const int* __restrict__ action,
             const float* __restrict__ Wa, const float* __restrict__ ba,
             const float* __restrict__ Wc, const float* __restrict__ bc,
             float* __restrict__ out)
{
    __shared__ float tile[64 * 129];     // transposed [k][r] with pad
    __shared__ float was[ACT * HID];
    __shared__ float bas[ACT];
    __shared__ float wcs[HID];
    __shared__ float bcs;

    const int tid = threadIdx.x;
    const int r0  = blockIdx.x * 128;
    const float* lat_pi = d_lat;
    const float* lat_vf = d_lat + (size_t)NROWS * HID;

    for (int i = tid; i < ACT * HID; i += 128) was[i] = Wa[i];
    if (tid < ACT) bas[tid] = ba[tid];
    if (tid < HID) wcs[tid] = Wc[tid];
    if (tid == 0)  bcs = bc[0];

    // stage lat_pi tile (transposed into smem, conflict-free both ways)
    for (int i = tid; i < 128 * HID; i += 128) {
        int r = i >> 6, k = i & 63;
        tile[k * 129 + r] = lat_pi[(size_t)r0 * HID + i];
    }
    __syncthreads();

    const int n = r0 + tid;
    float l[ACT];
    #pragma unroll
    for (int a = 0; a < ACT; a++) l[a] = bas[a];
    #pragma unroll 1
    for (int k = 0; k < HID; k++) {
        float x = tile[k * 129 + tid];
        #pragma unroll
        for (int a = 0; a < ACT; a++) l[a] = fmaf(was[a * HID + k], x, l[a]);
    }

    float m = l[0];
    #pragma unroll
    for (int a = 1; a < ACT; a++) m = fmaxf(m, l[a]);
    float se = 0.f;
    #pragma unroll
    for (int a = 0; a < ACT; a++) se += __expf(l[a] - m);
    float lse = m + __logf(se);
    float ent = 0.f;
    #pragma unroll
    for (int a = 0; a < ACT; a++) { float lp = l[a] - lse; ent += __expf(lp) * lp; }
    int   act    = action[n];
    float lpact  = l[act] - lse;
    __syncthreads();

    // stage lat_vf tile (reuse buffer)
    for (int i = tid; i < 128 * HID; i += 128) {
        int r = i >> 6, k = i & 63;
        tile[k * 129 + r] = lat_vf[(size_t)r0 * HID + i];
    }
    __syncthreads();

    float v = bcs;
    #pragma unroll
    for (int k = 0; k < HID; k++) v = fmaf(wcs[k], tile[k * 129 + tid], v);

    out[n]             = lpact;
    out[NROWS + n]     = -ent;
    out[2 * NROWS + n] = v;
}

// ---------------------------------------------------------------------------
extern "C" void kernel_launch(void* const* d_in, const int* in_sizes, int n_in,
                              void* d_out, int out_size)
{
    const float* obs     = (const float*)d_in[0];
    const int*   action  = (const int*)  d_in[1];
    const float* eps     = (const float*)d_in[2];
    const float* h_pi    = (const float*)d_in[3];
    const float* c_pi    = (const float*)d_in[4];
    const float* h_vf    = (const float*)d_in[5];
    const float* c_vf    = (const float*)d_in[6];
    const float* Wp1     = (const float*)d_in[7];
    const float* bp1     = (const float*)d_in[8];
    const float* Wp2     = (const float*)d_in[9];
    const float* bp2     = (const float*)d_in[10];
    const float* Wv1     = (const float*)d_in[11];
    const float* bv1     = (const float*)d_in[12];
    const float* Wv2     = (const float*)d_in[13];
    const float* bv2     = (const float*)d_in[14];
    const float* Wih_pi  = (const float*)d_in[15];
    const float* Whh_pi  = (const float*)d_in[16];
    const float* bih_pi  = (const float*)d_in[17];
    const float* bhh_pi  = (const float*)d_in[18];
    const float* Wih_vf  = (const float*)d_in[19];
    const float* Whh_vf  = (const float*)d_in[20];
    const float* bih_vf  = (const float*)d_in[21];
    const float* bhh_vf  = (const float*)d_in[22];
    const float* Wa      = (const float*)d_in[23];
    const float* ba      = (const float*)d_in[24];
    const float* Wc      = (const float*)d_in[25];
    const float* bc      = (const float*)d_in[26];
    float* out = (float*)d_out;

    const int SMEM = 114688;  // 28672 floats
    cudaFuncSetAttribute(mlp_gx_kernel, cudaFuncAttributeMaxDynamicSharedMemorySize, SMEM);

    mlp_gx_kernel<<<dim3(2048, 2), 128, SMEM>>>(obs,
        Wp1, bp1, Wp2, bp2, Wv1, bv1, Wv2, bv2,
        Wih_pi, bih_pi, bhh_pi, Wih_vf, bih_vf, bhh_vf);

    lstm_kernel<<<256, 256>>>(Whh_pi, Whh_vf, eps, h_pi, c_pi, h_vf, c_vf);

    heads_kernel<<<2048, 128>>>(action, Wa, ba, Wc, bc, out);
}

// round 3
// speedup vs baseline: 1.2070x; 1.2070x over previous
#include <cuda_runtime.h>
#include <cuda_fp16.h>
#include <mma.h>

using namespace nvcuda::wmma;

// ---------------------------------------------------------------------------
// LSTMActorCritic: NSEQ=256, T=1024, OBS=128, ACT=16, H=64, N=262144
//
//  K1 mlp_gx_kernel : tensor-core (HMMA fp16, fp32 accum) fused GEMM chain:
//                     obs[128x128] -> tanh L1[->64] -> tanh L2[->64] ->
//                     gates[->256] (+bih+bhh), per 128-row block, both
//                     branches via blockIdx.y. Writes gx fp32.
//  K2 lstm_kernel   : 256 blocks, each owns 2 sequences of ONE lstm for all
//                     1024 steps. Recurrent h@Whh.T with weights packed in
//                     registers (f32x2 over K), h broadcast from smem.
//  K3 heads_kernel  : logits/log_softmax/logprob/entropy + value.
// ---------------------------------------------------------------------------

typedef unsigned long long ull;

#define NSEQ   256
#define TLEN   1024
#define NROWS  262144      // NSEQ*TLEN
#define OBSD   128
#define HID    64
#define GATES  256         // 4*HID
#define ACT    16

// Scratch (no cudaMalloc allowed): gate pre-activations and LSTM outputs.
__device__ float d_gx [2ull * NROWS * GATES];   // 536 MB
__device__ float d_lat[2ull * NROWS * HID];     // 134 MB

// ---------------- packed fp32x2 helpers ----------------
__device__ __forceinline__ ull pk2(float lo, float hi) {
    ull r; asm("mov.b64 %0,{%1,%2};" : "=l"(r) : "f"(lo), "f"(hi)); return r;
}
__device__ __forceinline__ float hsum2(ull v) {
    float a, b; asm("mov.b64 {%0,%1}, %2;" : "=f"(a), "=f"(b) : "l"(v)); return a + b;
}
__device__ __forceinline__ void fma2(ull &acc, ull a, ull b) {
    asm("fma.rn.f32x2 %0,%1,%2,%0;" : "+l"(acc) : "l"(a), "l"(b));
}

__device__ __forceinline__ float sigmoidf_(float x) {
    return __fdividef(1.f, 1.f + __expf(-x));
}
__device__ __forceinline__ float tanhf_(float x) {
    float e = __expf(-2.f * fabsf(x));
    float t = __fdividef(1.f - e, 1.f + e);
    return copysignf(t, x);
}

// ---------------------------------------------------------------------------
// K1: tensor-core MLP + gate precompute.
// grid (2048, 2), block 256 (8 warps, warp w owns rows [16w,16w+16)).
//
// smem map (bytes, dynamic):
//   [0,      36864)  s_x   : obs tile fp16 128 x ld136  (aliased by s_f fp32 128 x ld72)
//   [36864,  53248)  s_w1  : W1 fp16, B col-major K=128 N=64, ld 128
//   [53248,  61440)  s_w2  : W2 fp16, col-major K=64 N=64, ld 64
//   [61440,  94208)  s_wih : Wih fp16, col-major K=64 N=256, ld 64
//   [94208, 112640)  s_a   : activations fp16 128 x ld72
//   [112640,114176)  biases: b1(64) b2(64) bg(256) fp32
// ---------------------------------------------------------------------------
extern "C" __global__ void __launch_bounds__(256)
mlp_gx_kernel(const float* __restrict__ obs,
              const float* __restrict__ Wp1, const float* __restrict__ bp1,
              const float* __restrict__ Wp2, const float* __restrict__ bp2,
              const float* __restrict__ Wv1, const float* __restrict__ bv1,
              const float* __restrict__ Wv2, const float* __restrict__ bv2,
              const float* __restrict__ Wih_pi, const float* __restrict__ bih_pi,
              const float* __restrict__ bhh_pi,
              const float* __restrict__ Wih_vf, const float* __restrict__ bih_vf,
              const float* __restrict__ bhh_vf)
{
    extern __shared__ char smem[];
    __half* s_x   = (__half*)(smem);             // ld 136
    float*  s_f   = (float*)(smem);              // ld 72 (alias of s_x)
    __half* s_w1  = (__half*)(smem + 36864);     // ld 128
    __half* s_w2  = (__half*)(smem + 53248);     // ld 64
    __half* s_wih = (__half*)(smem + 61440);     // ld 64
    __half* s_a   = (__half*)(smem + 94208);     // ld 72
    float*  s_b1  = (float*)(smem + 112640);
    float*  s_b2  = s_b1 + 64;
    float*  s_bg  = s_b2 + 64;

    const int tid    = threadIdx.x;
    const int warp   = tid >> 5;
    const int branch = blockIdx.y;

    const float* W1  = branch ? Wv1 : Wp1;
    const float* b1  = branch ? bv1 : bp1;
    const float* W2  = branch ? Wv2 : Wp2;
    const float* b2  = branch ? bv2 : bp2;
    const float* Wih = branch ? Wih_vf : Wih_pi;
    const float* bih = branch ? bih_vf : bih_pi;
    const float* bhh = branch ? bhh_vf : bhh_pi;
    float* gx = d_gx + (size_t)branch * NROWS * GATES;

    // stage weights (fp32 -> fp16) and biases
    for (int i = tid; i < 8192;  i += 256) s_w1[i]  = __float2half(W1[i]);
    for (int i = tid; i < 4096;  i += 256) s_w2[i]  = __float2half(W2[i]);
    for (int i = tid; i < 16384; i += 256) s_wih[i] = __float2half(Wih[i]);
    if (tid < 64)       s_b1[tid]       = b1[tid];
    else if (tid < 128) s_b2[tid - 64]  = b2[tid - 64];
    s_bg[tid] = bih[tid] + bhh[tid];

    // stage obs tile fp16
    const size_t row0 = (size_t)blockIdx.x * 128;
    for (int i = tid; i < 128 * 128; i += 256) {
        int r = i >> 7, k = i & 127;
        s_x[r * 136 + k] = __float2half(obs[(row0 + r) * OBSD + k]);
    }
    __syncthreads();

    fragment<matrix_a, 16, 16, 16, __half, row_major> fa;
    fragment<matrix_b, 16, 16, 16, __half, col_major> fb;
    fragment<accumulator, 16, 16, 16, float> fc[4];

    // ---- Layer 1: [128x128] @ [128x64] ----
    #pragma unroll
    for (int n = 0; n < 4; n++) fill_fragment(fc[n], 0.0f);
    #pragma unroll
    for (int k = 0; k < 8; k++) {
        load_matrix_sync(fa, s_x + warp * 16 * 136 + k * 16, 136);
        #pragma unroll
        for (int n = 0; n < 4; n++) {
            load_matrix_sync(fb, s_w1 + n * 16 * 128 + k * 16, 128);
            mma_sync(fc[n], fa, fb, fc[n]);
        }
    }
    __syncthreads();                       // all warps done reading s_x
    #pragma unroll
    for (int n = 0; n < 4; n++)
        store_matrix_sync(s_f + warp * 16 * 72 + n * 16, fc[n], 72, mem_row_major);
    __syncthreads();
    for (int i = tid; i < 128 * 64; i += 256) {
        int r = i >> 6, c = i & 63;
        s_a[r * 72 + c] = __float2half(tanhf_(s_f[r * 72 + c] + s_b1[c]));
    }
    __syncthreads();

    // ---- Layer 2: [128x64] @ [64x64] ----
    #pragma unroll
    for (int n = 0; n < 4; n++) fill_fragment(fc[n], 0.0f);
    #pragma unroll
    for (int k = 0; k < 4; k++) {
        load_matrix_sync(fa, s_a + warp * 16 * 72 + k * 16, 72);
        #pragma unroll
        for (int n = 0; n < 4; n++) {
            load_matrix_sync(fb, s_w2 + n * 16 * 64 + k * 16, 64);
            mma_sync(fc[n], fa, fb, fc[n]);
        }
    }
    #pragma unroll
    for (int n = 0; n < 4; n++)
        store_matrix_sync(s_f + warp * 16 * 72 + n * 16, fc[n], 72, mem_row_major);
    __syncthreads();                       // mma reads of s_a done + s_f stores visible
    for (int i = tid; i < 128 * 64; i += 256) {
        int r = i >> 6, c = i & 63;
        s_a[r * 72 + c] = __float2half(tanhf_(s_f[r * 72 + c] + s_b2[c]));
    }
    __syncthreads();

    // ---- Gates: [128x64] @ [64x256], 4 chunks of 64 cols ----
    float* gxp = gx + row0 * GATES;
    #pragma unroll 1
    for (int ch = 0; ch < 4; ch++) {
        #pragma unroll
        for (int n = 0; n < 4; n++) fill_fragment(fc[n], 0.0f);
        #pragma unroll
        for (int k = 0; k < 4; k++) {
            load_matrix_sync(fa, s_a + warp * 16 * 72 + k * 16, 72);
            #pragma unroll
            for (int n = 0; n < 4; n++) {
                load_matrix_sync(fb, s_wih + (ch * 64 + n * 16) * 64 + k * 16, 64);
                mma_sync(fc[n], fa, fb, fc[n]);
            }
        }
        #pragma unroll
        for (int n = 0; n < 4; n++)
            store_matrix_sync(s_f + warp * 16 * 72 + n * 16, fc[n], 72, mem_row_major);
        __syncthreads();
        for (int i = tid; i < 128 * 64; i += 256) {
            int r = i >> 6, c = i & 63;
            gxp[(size_t)r * GATES + ch * 64 + c] = s_f[r * 72 + c] + s_bg[ch * 64 + c];
        }
        __syncthreads();
    }
}

// ---------------------------------------------------------------------------
// K2: recurrent loop. grid 256 blocks (bit7 = lstm, low bits = seq pair),
// 256 threads: thread j computes gate j for both of its 2 sequences (shared
// weight row in registers). Threads 0..127 apply the elementwise update.
// ---------------------------------------------------------------------------
extern "C" __global__ void __launch_bounds__(256, 2)
lstm_kernel(const float* __restrict__ Whh_pi, const float* __restrict__ Whh_vf,
            const float* __restrict__ eps,
            const float* __restrict__ h0_pi, const float* __restrict__ c0_pi,
            const float* __restrict__ h0_vf, const float* __restrict__ c0_vf)
{
    const int tid  = threadIdx.x;
    const int lstm = blockIdx.x >> 7;
    const int sp   = blockIdx.x & 127;
    const int seqA = sp * 2, seqB = sp * 2 + 1;

    const float* Whh = lstm ? Whh_vf : Whh_pi;
    const float* h0  = lstm ? h0_vf  : h0_pi;
    const float* c0  = lstm ? c0_vf  : c0_pi;
    const float* gx  = d_gx  + (size_t)lstm * NROWS * GATES;
    float*       lat = d_lat + (size_t)lstm * NROWS * HID;

    __shared__ __align__(16) float hs[2][HID];
    __shared__ float gs[2][GATES];

    // Whh row tid -> 32 packed pairs in registers
    ull wv[32];
    {
        const float4* wp = (const float4*)(Whh + tid * HID);
        #pragma unroll
        for (int i = 0; i < 16; i++) {
            float4 v = wp[i];
            wv[2*i]   = pk2(v.x, v.y);
            wv[2*i+1] = pk2(v.z, v.w);
        }
    }

    const int s = tid >> 6, j = tid & 63;      // valid for tid < 128
    const int myseq = seqA + s;
    float c = 0.f, enext = 0.f;
    if (tid < 128) {
        float m = 1.f - eps[(size_t)myseq * TLEN];
        hs[s][j] = h0[myseq * HID + j] * m;
        c        = c0[myseq * HID + j] * m;
        enext    = eps[(size_t)myseq * TLEN + 1];
    }
    __syncthreads();

    float gA = gx[((size_t)seqA * TLEN) * GATES + tid];
    float gB = gx[((size_t)seqB * TLEN) * GATES + tid];

    const ulonglong2* hA2 = (const ulonglong2*)hs[0];
    const ulonglong2* hB2 = (const ulonglong2*)hs[1];

    for (int t = 0; t < TLEN; t++) {
        ull a0 = 0, a1 = 0, b0 = 0, b1_ = 0;
        #pragma unroll
        for (int kk = 0; kk < 16; kk++) {
            ulonglong2 ha = hA2[kk]; ulonglong2 hb = hB2[kk];
            fma2(a0,  wv[2*kk],   ha.x);  fma2(a1,  wv[2*kk+1], ha.y);
            fma2(b0,  wv[2*kk],   hb.x);  fma2(b1_, wv[2*kk+1], hb.y);
        }
        float gateA = gA + hsum2(a0) + hsum2(a1);
        float gateB = gB + hsum2(b0) + hsum2(b1_);

        // software-pipelined prefetch for step t+1 / mask for t+2
        if (t < TLEN - 1) {
            gA = gx[((size_t)seqA * TLEN + t + 1) * GATES + tid];
            gB = gx[((size_t)seqB * TLEN + t + 1) * GATES + tid];
        }
        float e2 = 0.f;
        if (tid < 128 && t < TLEN - 2) e2 = eps[(size_t)myseq * TLEN + t + 2];

        gs[0][tid] = gateA;
        gs[1][tid] = gateB;
        __syncthreads();

        if (tid < 128) {
            float gi = gs[s][j],       gf = gs[s][64 + j];
            float gg = gs[s][128 + j], go = gs[s][192 + j];
            c = sigmoidf_(gf) * c + sigmoidf_(gi) * tanhf_(gg);
            float h = sigmoidf_(go) * tanhf_(c);
            lat[((size_t)myseq * TLEN + t) * HID + j] = h;
            float m = 1.f - enext;    // mask for step t+1
            c *= m;
            hs[s][j] = h * m;
            enext = e2;
        }
        __syncthreads();
    }
}

// ---------------------------------------------------------------------------
// K3: heads. grid 2048 blocks, 128 threads, block handles 128 rows.
// ---------------------------------------------------------------------------
extern "C" __global__ void __launch_bounds__(128)
heads_kernel(const int* __restrict__ action,
             const float* __restrict__ Wa, const float* __restrict__ ba,
             const float* __restrict__ Wc, const float* __restrict__ bc,
             float* __restrict__ out)
{
    __shared__ float tile[64 * 129];     // transposed [k][r] with pad
    __shared__ float was[ACT * HID];
    __shared__ float bas[ACT];
    __shared__ float wcs[HID];
    __shared__ float bcs;

    const int tid = threadIdx.x;
    const int r0  = blockIdx.x * 128;
    const float* lat_pi = d_lat;
    const float* lat_vf = d_lat + (size_t)NROWS * HID;

    for (int i = tid; i < ACT * HID; i += 128) was[i] = Wa[i];
    if (tid < ACT) bas[tid] = ba[tid];
    if (tid < HID) wcs[tid] = Wc[tid];
    if (tid == 0)  bcs = bc[0];

    for (int i = tid; i < 128 * HID; i += 128) {
        int r = i >> 6, k = i & 63;
        tile[k * 129 + r] = lat_pi[(size_t)r0 * HID + i];
    }
    __syncthreads();

    const int n = r0 + tid;
    float l[ACT];
    #pragma unroll
    for (int a = 0; a < ACT; a++) l[a] = bas[a];
    #pragma unroll 1
    for (int k = 0; k < HID; k++) {
        float x = tile[k * 129 + tid];
        #pragma unroll
        for (int a = 0; a < ACT; a++) l[a] = fmaf(was[a * HID + k], x, l[a]);
    }

    float m = l[0];
    #pragma unroll
    for (int a = 1; a < ACT; a++) m = fmaxf(m, l[a]);
    float se = 0.f;
    #pragma unroll
    for (int a = 0; a < ACT; a++) se += __expf(l[a] - m);
    float lse = m + __logf(se);
    float ent = 0.f;
    #pragma unroll
    for (int a = 0; a < ACT; a++) { float lp = l[a] - lse; ent += __expf(lp) * lp; }
    int   act    = action[n];
    float lpact  = l[act] - lse;
    __syncthreads();

    for (int i = tid; i < 128 * HID; i += 128) {
        int r = i >> 6, k = i & 63;
        tile[k * 129 + r] = lat_vf[(size_t)r0 * HID + i];
    }
    __syncthreads();

    float v = bcs;
    #pragma unroll
    for (int k = 0; k < HID; k++) v = fmaf(wcs[k], tile[k * 129 + tid], v);

    out[n]             = lpact;
    out[NROWS + n]     = -ent;
    out[2 * NROWS + n] = v;
}

// ---------------------------------------------------------------------------
extern "C" void kernel_launch(void* const* d_in, const int* in_sizes, int n_in,
                              void* d_out, int out_size)
{
    const float* obs     = (const float*)d_in[0];
    const int*   action  = (const int*)  d_in[1];
    const float* eps     = (const float*)d_in[2];
    const float* h_pi    = (const float*)d_in[3];
    const float* c_pi    = (const float*)d_in[4];
    const float* h_vf    = (const float*)d_in[5];
    const float* c_vf    = (const float*)d_in[6];
    const float* Wp1     = (const float*)d_in[7];
    const float* bp1     = (const float*)d_in[8];
    const float* Wp2     = (const float*)d_in[9];
    const float* bp2     = (const float*)d_in[10];
    const float* Wv1     = (const float*)d_in[11];
    const float* bv1     = (const float*)d_in[12];
    const float* Wv2     = (const float*)d_in[13];
    const float* bv2     = (const float*)d_in[14];
    const float* Wih_pi  = (const float*)d_in[15];
    const float* Whh_pi  = (const float*)d_in[16];
    const float* bih_pi  = (const float*)d_in[17];
    const float* bhh_pi  = (const float*)d_in[18];
    const float* Wih_vf  = (const float*)d_in[19];
    const float* Whh_vf  = (const float*)d_in[20];
    const float* bih_vf  = (const float*)d_in[21];
    const float* bhh_vf  = (const float*)d_in[22];
    const float* Wa      = (const float*)d_in[23];
    const float* ba      = (const float*)d_in[24];
    const float* Wc      = (const float*)d_in[25];
    const float* bc      = (const float*)d_in[26];
    float* out = (float*)d_out;

    const int SMEM = 114688;
    cudaFuncSetAttribute(mlp_gx_kernel, cudaFuncAttributeMaxDynamicSharedMemorySize, SMEM);

    mlp_gx_kernel<<<dim3(2048, 2), 256, SMEM>>>(obs,
        Wp1, bp1, Wp2, bp2, Wv1, bv1, Wv2, bv2,
        Wih_pi, bih_pi, bhh_pi, Wih_vf, bih_vf, bhh_vf);

    lstm_kernel<<<256, 256>>>(Whh_pi, Whh_vf, eps, h_pi, c_pi, h_vf, c_vf);

    heads_kernel<<<2048, 128>>>(action, Wa, ba, Wc, bc, out);
}